// round 12
// baseline (speedup 1.0000x reference)
#include <cuda_runtime.h>
#include <math.h>
#include <stdint.h>

#define N_PAT 4096
#define DIM   256
#define EPSV  1e-8f
#define RBLK  32                  // rows per prep block
#define NRB   (N_PAT / RBLK)      // 128 row-blocks per modality
#define NPREP (4 * NRB)           // 512 prep blocks
#define NBKT  4096
#define FXSCALE 1048576.0f        // 2^20 fixed-point for deterministic scatter
#define NFIN  9                   // finish blocks: 0 = cox+VW, 1..8 = U^2 slices

// ---------------- static scratch ----------------
__device__ float  g_upart[NPREP * DIM];   // [prep block][col]
__device__ float2 g_vw[NPREP];            // per (mod,rowblock) (V,W)
__device__ float  g_U2part[8];            // per (mod, col-half) sum of u^2
__device__ float  g_V[4], g_W[4];         // per-mod V, W
__device__ float  g_coxsum, g_efsum;
__device__ int    g_count;                // arrival counter (reset by last block)

// ---------------- prep: row stats + weighted column partial sums ----------------
__global__ void __launch_bounds__(256)
prep_kernel(const float* __restrict__ eb0, const float* __restrict__ eb1,
            const float* __restrict__ eb2, const float* __restrict__ eb3) {
    __shared__ float smf[2048];
    __shared__ float snm[8], sww[8];

    int mod = blockIdx.x >> 7;
    int rb  = blockIdx.x & 127;
    int r0  = rb * RBLK;
    const float* base = (mod == 0) ? eb0 : (mod == 1) ? eb1
                      : (mod == 2) ? eb2 : eb3;
    int tid = threadIdx.x;
    int w = tid >> 5, lane = tid & 31;

    float4 va[4], vb[4];
#pragma unroll
    for (int rr = 0; rr < 4; rr++) {
        const float4* src = (const float4*)(base + (size_t)(r0 + w * 4 + rr) * DIM);
        va[rr] = src[lane];
        vb[rr] = src[lane + 32];
    }

    float4 acc0 = make_float4(0.f, 0.f, 0.f, 0.f);
    float4 acc1 = make_float4(0.f, 0.f, 0.f, 0.f);
    float nmW = 0.0f, wW = 0.0f;
#pragma unroll
    for (int rr = 0; rr < 4; rr++) {
        float4 v0 = va[rr], v1 = vb[rr];
        float x0 = __shfl_sync(0xffffffffu, v0.x, 0);
        bool eq = (v0.x == x0) && (v0.y == x0) && (v0.z == x0) && (v0.w == x0) &&
                  (v1.x == x0) && (v1.y == x0) && (v1.z == x0) && (v1.w == x0);
        bool miss = (__ballot_sync(0xffffffffu, eq) == 0xffffffffu);

        float ss = v0.x*v0.x + v0.y*v0.y + v0.z*v0.z + v0.w*v0.w
                 + v1.x*v1.x + v1.y*v1.y + v1.z*v1.z + v1.w*v1.w;
#pragma unroll
        for (int o = 16; o > 0; o >>= 1) ss += __shfl_xor_sync(0xffffffffu, ss, o);

        float den = fmaxf(sqrtf(ss), EPSV);
        float inv = miss ? 0.0f : (1.0f / den);
        if (!miss) { nmW += 1.0f; wW += ss / (den * den); }

        acc0.x += v0.x * inv; acc0.y += v0.y * inv;
        acc0.z += v0.z * inv; acc0.w += v0.w * inv;
        acc1.x += v1.x * inv; acc1.y += v1.y * inv;
        acc1.z += v1.z * inv; acc1.w += v1.w * inv;
    }

    float* row = smf + w * 256;
    *(float4*)(row + lane * 4)       = acc0;
    *(float4*)(row + 128 + lane * 4) = acc1;
    if (lane == 0) { snm[w] = nmW; sww[w] = wW; }
    __syncthreads();

    float u = 0.0f;
#pragma unroll
    for (int ww = 0; ww < 8; ww++) u += smf[ww * 256 + tid];
    g_upart[((size_t)blockIdx.x << 8) + tid] = u;

    if (tid == 0) {
        float V = 0.0f, W = 0.0f;
#pragma unroll
        for (int i = 0; i < 8; i++) { V += snm[i]; W += sww[i]; }
        g_vw[blockIdx.x] = make_float2(V, W);
    }
}

// ---------------- finish: 9 blocks + deterministic last-block combine ----------------
__global__ void __launch_bounds__(1024)
finish_kernel(const float* __restrict__ h, const int* __restrict__ t,
              const int* __restrict__ e, const int* __restrict__ mptr,
              float* __restrict__ out) {
    __shared__ __align__(16) unsigned long long bkt[NBKT];   // 32KB (aliased as S)
    __shared__ float rv[1024];
    __shared__ float rw[1024];
    __shared__ int s_last;
    float* S = (float*)bkt;
    int tid = threadIdx.x;
    int b = blockIdx.x;

    if (b == 0) {
        // ======== cox: fixed-point histogram + suffix scan + lookup ========
#pragma unroll
        for (int k = 0; k < 4; k++) bkt[tid + k * 1024] = 0ull;
        __syncthreads();

        int   tv[4];
        float hv[4];
#pragma unroll
        for (int k = 0; k < 4; k++) {
            int i = tid + k * 1024;
            tv[k] = t[i] & (NBKT - 1);
            hv[k] = h[i];
            unsigned long long q = (unsigned long long)(expf(hv[k]) * FXSCALE);
            atomicAdd(&bkt[tv[k]], q);
        }
        __syncthreads();

        int base = tid * 4;
        float b0 = (float)bkt[base + 0] * (1.0f / FXSCALE);
        float b1 = (float)bkt[base + 1] * (1.0f / FXSCALE);
        float b2 = (float)bkt[base + 2] * (1.0f / FXSCALE);
        float b3 = (float)bkt[base + 3] * (1.0f / FXSCALE);
        float cs = b0 + b1 + b2 + b3;
        rv[tid] = cs;
        __syncthreads();
#pragma unroll
        for (int o = 1; o < 1024; o <<= 1) {
            float v = (tid + o < 1024) ? rv[tid + o] : 0.0f;
            __syncthreads();
            rv[tid] += v;
            __syncthreads();
        }
        float excl = rv[tid] - cs;
        float s3 = excl + b3;
        float s2 = s3 + b2;
        float s1 = s2 + b1;
        float s0 = s1 + b0;
        S[base + 0] = s0; S[base + 1] = s1; S[base + 2] = s2; S[base + 3] = s3;
        __syncthreads();

        float cp = 0.0f, ef = 0.0f;
#pragma unroll
        for (int k = 0; k < 4; k++) {
            int i = tid + k * 1024;
            int ei = e[i];
            ef += (float)ei;
            if (ei) cp += hv[k] - logf(S[tv[k]]);
        }
        __syncthreads();

        // cox reduce
        rv[tid] = cp; rw[tid] = ef;
        __syncthreads();
#pragma unroll
        for (int o = 512; o > 0; o >>= 1) {
            if (tid < o) { rv[tid] += rv[tid + o]; rw[tid] += rw[tid + o]; }
            __syncthreads();
        }
        if (tid == 0) { g_coxsum = rv[0]; g_efsum = rw[0]; }

        // ======== per-mod V, W ========
        {
            float V = 0.0f, W = 0.0f;
            if (tid < NPREP) { float2 vw = g_vw[tid]; V = vw.x; W = vw.y; }
            __syncthreads();
            rv[tid] = V; rw[tid] = W;
        }
        __syncthreads();
#pragma unroll
        for (int o = NRB / 2; o > 0; o >>= 1) {
            if (tid < NPREP && (tid & (NRB - 1)) < o) {
                rv[tid] += rv[tid + o];
                rw[tid] += rw[tid + o];
            }
            __syncthreads();
        }
        if (tid < 4) { g_V[tid] = rv[tid * NRB]; g_W[tid] = rw[tid * NRB]; }
    } else {
        // ======== U^2 slice: mod = (b-1)>>1, column half = (b-1)&1 ========
        int idx  = b - 1;
        int mod  = idx >> 1;
        int half = idx & 1;
        int col  = (tid & 127) + half * 128;
        int rg   = tid >> 7;              // 0..7, each covers 16 rb
        const float* up = g_upart + (((size_t)(mod * 128 + rg * 16)) << 8) + col;
        float u = 0.0f;
#pragma unroll
        for (int k = 0; k < 16; k++) u += up[(size_t)k << 8];
        rv[tid] = u;
        __syncthreads();
        if (tid < 128) {
            float ut = 0.0f;
#pragma unroll
            for (int g = 0; g < 8; g++) ut += rv[g * 128 + tid];
            rw[tid] = ut * ut;
        }
        __syncthreads();
#pragma unroll
        for (int o = 64; o > 0; o >>= 1) {
            if (tid < o) rw[tid] += rw[tid + o];
            __syncthreads();
        }
        if (tid == 0) g_U2part[idx] = rw[0];
    }

    // ======== deterministic last-block combine ========
    __threadfence();
    if (tid == 0) {
        int c = atomicAdd(&g_count, 1);
        s_last = (c == NFIN - 1);
    }
    __syncthreads();
    if (s_last && tid == 0) {
        int iv = mptr[0];
        float margin = (iv > -1000000 && iv < 1000000) ? (float)iv : __int_as_float(iv);

        double sim = (double)margin * (double)N_PAT * (double)(N_PAT - 1);
#pragma unroll
        for (int m = 0; m < 4; m++)
            sim += (double)g_W[m] * (double)g_V[m]
                 - (double)g_U2part[2 * m] - (double)g_U2part[2 * m + 1];
        double cox = -(double)g_coxsum / (double)g_efsum;
        out[0] = (float)(sim + cox);
        g_count = 0;            // reset for next graph replay
    }
}

// ---------------- launch ----------------
extern "C" void kernel_launch(void* const* d_in, const int* in_sizes, int n_in,
                              void* d_out, int out_size) {
    const float* h   = (const float*)d_in[0];
    const int*   t   = (const int*)d_in[1];
    const int*   e   = (const int*)d_in[2];
    const float* eb0 = (const float*)d_in[3];
    const float* eb1 = (const float*)d_in[4];
    const float* eb2 = (const float*)d_in[5];
    const float* eb3 = (const float*)d_in[6];
    const int*   mg  = (const int*)d_in[7];
    float* out = (float*)d_out;

    prep_kernel<<<NPREP, 256>>>(eb0, eb1, eb2, eb3);
    finish_kernel<<<NFIN, 1024>>>(h, t, e, mg, out);
}

// round 13
// speedup vs baseline: 1.0328x; 1.0328x over previous
#include <cuda_runtime.h>
#include <math.h>
#include <stdint.h>

#define N_PAT 4096
#define DIM   256
#define EPSV  1e-8f
#define RBLK  32                  // rows per prep block
#define NRB   (N_PAT / RBLK)      // 128 row-blocks per modality
#define NPREP (4 * NRB)           // 512 prep blocks
#define NBKT  4096
#define FXSCALE 1048576.0f        // 2^20 fixed-point for deterministic scatter
#define NFIN  8                   // finish blocks: U^2 slices

// ---------------- static scratch ----------------
__device__ float  g_upart[NPREP * DIM];   // [prep block][col]
__device__ float2 g_vw[NPREP];            // per (mod,rowblock) (V,W)
__device__ float  g_U2part[8];            // per (mod, col-half) sum of u^2
__device__ float  g_V[4], g_W[4];         // per-mod V, W
__device__ float  g_coxsum, g_efsum;
__device__ int    g_count;                // arrival counter (reset by last block)

// =================== kernel 1: cox block + 512 prep blocks ===================
__global__ void __launch_bounds__(256)
main_kernel(const float* __restrict__ h, const int* __restrict__ t,
            const int* __restrict__ e,
            const float* __restrict__ eb0, const float* __restrict__ eb1,
            const float* __restrict__ eb2, const float* __restrict__ eb3) {
    __shared__ __align__(16) unsigned long long bkt[NBKT];   // 32KB; cox only
    __shared__ float smf[2048];                              // prep col partials / cox partials
    __shared__ float snm[8], sww[8];
    float* S = (float*)bkt;

    int tid = threadIdx.x;
    int w = tid >> 5, lane = tid & 31;

    if (blockIdx.x == 0) {
        // ================= cox: histogram + warp-suffix-scan + lookup =================
#pragma unroll
        for (int k = 0; k < 16; k++) bkt[tid + k * 256] = 0ull;
        __syncthreads();

        int   tv[16];
        float hv[16];
#pragma unroll
        for (int k = 0; k < 16; k++) {
            int i = tid + k * 256;
            tv[k] = t[i] & (NBKT - 1);
            hv[k] = h[i];
            unsigned long long q = (unsigned long long)(expf(hv[k]) * FXSCALE);
            atomicAdd(&bkt[tv[k]], q);
        }
        __syncthreads();

        // per-thread chunk of 16 buckets -> registers
        float b[16];
        float cs = 0.0f;
#pragma unroll
        for (int j = 0; j < 16; j++) {
            b[j] = (float)bkt[tid * 16 + j] * (1.0f / FXSCALE);
            cs += b[j];
        }
        // warp suffix-inclusive scan of chunk sums (lane i gets sum of lanes i..31)
        float suf = cs;
#pragma unroll
        for (int o = 1; o < 32; o <<= 1) {
            float v = __shfl_down_sync(0xffffffffu, suf, o);
            if (lane + o < 32) suf += v;
        }
        if (lane == 0) snm[w] = suf;     // warp total
        __syncthreads();                 // also orders bkt reads before S writes

        float wse = 0.0f;                // suffix-exclusive over warps
        for (int ww = w + 1; ww < 8; ww++) wse += snm[ww];
        float excl = wse + (suf - cs);   // everything strictly after this chunk
        float s = excl;
#pragma unroll
        for (int j = 15; j >= 0; j--) {
            s += b[j];
            S[tid * 16 + j] = s;
        }
        __syncthreads();

        // lookups
        float cp = 0.0f, ef = 0.0f;
#pragma unroll
        for (int k = 0; k < 16; k++) {
            int i = tid + k * 256;
            int ei = e[i];
            ef += (float)ei;
            if (ei) cp += hv[k] - logf(S[tv[k]]);
        }
        // warp reduce then cross-warp
#pragma unroll
        for (int o = 16; o > 0; o >>= 1) {
            cp += __shfl_xor_sync(0xffffffffu, cp, o);
            ef += __shfl_xor_sync(0xffffffffu, ef, o);
        }
        if (lane == 0) { snm[w] = cp; sww[w] = ef; }
        __syncthreads();
        if (tid == 0) {
            float tc = 0.0f, te = 0.0f;
#pragma unroll
            for (int i = 0; i < 8; i++) { tc += snm[i]; te += sww[i]; }
            g_coxsum = tc; g_efsum = te;
        }

        // ================= V, W reduction (512 float2) =================
        // thread tid handles entries tid (mod tid>>7) and tid+256 (mod (tid>>7)+2)
        float2 va = g_vw[tid];
        float2 vb = g_vw[tid + 256];
        float Va = va.x, Wa = va.y, Vb = vb.x, Wb = vb.y;
#pragma unroll
        for (int o = 16; o > 0; o >>= 1) {
            Va += __shfl_xor_sync(0xffffffffu, Va, o);
            Wa += __shfl_xor_sync(0xffffffffu, Wa, o);
            Vb += __shfl_xor_sync(0xffffffffu, Vb, o);
            Wb += __shfl_xor_sync(0xffffffffu, Wb, o);
        }
        if (lane == 0) {
            // warps 0-3: mods 0 & 2 ; warps 4-7: mods 1 & 3
            smf[w] = Va; smf[8 + w] = Wa; smf[16 + w] = Vb; smf[24 + w] = Wb;
        }
        __syncthreads();
        if (tid < 4) {
            int m = tid;                      // target mod
            int base = (m & 1) ? 4 : 0;       // warps 4..7 for odd mods
            int off  = (m >> 1) ? 16 : 0;     // Vb/Wb arrays for mods 2,3
            float V = 0.0f, W = 0.0f;
#pragma unroll
            for (int k = 0; k < 4; k++) {
                V += smf[off + base + k];
                W += smf[8 + off + base + k];
            }
            g_V[m] = V; g_W[m] = W;
        }
    } else {
        // ================= prep =================
        int pb  = blockIdx.x - 1;
        int mod = pb >> 7;
        int rb  = pb & 127;
        int r0  = rb * RBLK;
        const float* base = (mod == 0) ? eb0 : (mod == 1) ? eb1
                          : (mod == 2) ? eb2 : eb3;

        float4 va[4], vb[4];
#pragma unroll
        for (int rr = 0; rr < 4; rr++) {
            const float4* src = (const float4*)(base + (size_t)(r0 + w * 4 + rr) * DIM);
            va[rr] = src[lane];
            vb[rr] = src[lane + 32];
        }

        float4 acc0 = make_float4(0.f, 0.f, 0.f, 0.f);
        float4 acc1 = make_float4(0.f, 0.f, 0.f, 0.f);
        float nmW = 0.0f, wW = 0.0f;
#pragma unroll
        for (int rr = 0; rr < 4; rr++) {
            float4 v0 = va[rr], v1 = vb[rr];
            float x0 = __shfl_sync(0xffffffffu, v0.x, 0);
            bool eq = (v0.x == x0) && (v0.y == x0) && (v0.z == x0) && (v0.w == x0) &&
                      (v1.x == x0) && (v1.y == x0) && (v1.z == x0) && (v1.w == x0);
            bool miss = (__ballot_sync(0xffffffffu, eq) == 0xffffffffu);

            float ss = v0.x*v0.x + v0.y*v0.y + v0.z*v0.z + v0.w*v0.w
                     + v1.x*v1.x + v1.y*v1.y + v1.z*v1.z + v1.w*v1.w;
#pragma unroll
            for (int o = 16; o > 0; o >>= 1) ss += __shfl_xor_sync(0xffffffffu, ss, o);

            float den = fmaxf(sqrtf(ss), EPSV);
            float inv = miss ? 0.0f : (1.0f / den);
            if (!miss) { nmW += 1.0f; wW += ss / (den * den); }

            acc0.x += v0.x * inv; acc0.y += v0.y * inv;
            acc0.z += v0.z * inv; acc0.w += v0.w * inv;
            acc1.x += v1.x * inv; acc1.y += v1.y * inv;
            acc1.z += v1.z * inv; acc1.w += v1.w * inv;
        }

        float* row = smf + w * 256;
        *(float4*)(row + lane * 4)       = acc0;
        *(float4*)(row + 128 + lane * 4) = acc1;
        if (lane == 0) { snm[w] = nmW; sww[w] = wW; }
        __syncthreads();

        float u = 0.0f;
#pragma unroll
        for (int ww = 0; ww < 8; ww++) u += smf[ww * 256 + tid];
        g_upart[((size_t)pb << 8) + tid] = u;

        if (tid == 0) {
            float V = 0.0f, W = 0.0f;
#pragma unroll
            for (int i = 0; i < 8; i++) { V += snm[i]; W += sww[i]; }
            g_vw[pb] = make_float2(V, W);
        }
    }
}

// =================== kernel 2: U^2 slices + last-block combine ===================
__global__ void __launch_bounds__(1024)
finish_kernel(const int* __restrict__ mptr, float* __restrict__ out) {
    __shared__ float rv[1024];
    __shared__ float rw[128];
    __shared__ int s_last;
    int tid = threadIdx.x;

    // slice: mod = b>>1, column half = b&1
    int mod  = blockIdx.x >> 1;
    int half = blockIdx.x & 1;
    int col  = (tid & 127) + half * 128;
    int rg   = tid >> 7;              // 0..7, each covers 16 rb
    const float* up = g_upart + (((size_t)(mod * 128 + rg * 16)) << 8) + col;
    float u = 0.0f;
#pragma unroll
    for (int k = 0; k < 16; k++) u += up[(size_t)k << 8];
    rv[tid] = u;
    __syncthreads();
    if (tid < 128) {
        float ut = 0.0f;
#pragma unroll
        for (int g = 0; g < 8; g++) ut += rv[g * 128 + tid];
        rw[tid] = ut * ut;
    }
    __syncthreads();
    if (tid < 32) {
        float x = rw[tid] + rw[tid + 32] + rw[tid + 64] + rw[tid + 96];
#pragma unroll
        for (int o = 16; o > 0; o >>= 1) x += __shfl_xor_sync(0xffffffffu, x, o);
        if (tid == 0) g_U2part[blockIdx.x] = x;
    }

    __threadfence();
    if (tid == 0) {
        int c = atomicAdd(&g_count, 1);
        s_last = (c == NFIN - 1);
    }
    __syncthreads();
    if (s_last && tid == 0) {
        int iv = mptr[0];
        float margin = (iv > -1000000 && iv < 1000000) ? (float)iv : __int_as_float(iv);

        double sim = (double)margin * (double)N_PAT * (double)(N_PAT - 1);
#pragma unroll
        for (int m = 0; m < 4; m++)
            sim += (double)g_W[m] * (double)g_V[m]
                 - (double)g_U2part[2 * m] - (double)g_U2part[2 * m + 1];
        double cox = -(double)g_coxsum / (double)g_efsum;
        out[0] = (float)(sim + cox);
        g_count = 0;            // reset for next graph replay
    }
}

// ---------------- launch ----------------
extern "C" void kernel_launch(void* const* d_in, const int* in_sizes, int n_in,
                              void* d_out, int out_size) {
    const float* h   = (const float*)d_in[0];
    const int*   t   = (const int*)d_in[1];
    const int*   e   = (const int*)d_in[2];
    const float* eb0 = (const float*)d_in[3];
    const float* eb1 = (const float*)d_in[4];
    const float* eb2 = (const float*)d_in[5];
    const float* eb3 = (const float*)d_in[6];
    const int*   mg  = (const int*)d_in[7];
    float* out = (float*)d_out;

    main_kernel<<<NPREP + 1, 256>>>(h, t, e, eb0, eb1, eb2, eb3);
    finish_kernel<<<NFIN, 1024>>>(mg, out);
}

// round 14
// speedup vs baseline: 1.1345x; 1.0985x over previous
#include <cuda_runtime.h>
#include <math.h>
#include <stdint.h>

#define N_PAT 4096
#define DIM   256
#define EPSV  1e-8f
#define RBLK  32                  // rows per prep block
#define NRB   (N_PAT / RBLK)      // 128 row-blocks per modality
#define NPREP (4 * NRB)           // 512 prep blocks
#define NBLK  (NPREP + 1)         // + cox block
#define NBKT  4096
#define FXSCALE 1048576.0f        // 2^20 fixed-point for cox histogram
#define FXU     16777216.0f       // 2^24 fixed-point for u accumulators

// ---------------- static scratch ----------------
__device__ unsigned long long g_uFx[4 * DIM];   // per (mod,col) fixed-point u sum
__device__ float2 g_vw[NPREP];                  // per (mod,rowblock) (V,W)
__device__ float  g_coxsum, g_efsum;
__device__ int    g_count;                      // arrival counter (reset by last block)

// =================== single kernel: cox + prep + last-block combine ===================
__global__ void __launch_bounds__(256)
main_kernel(const float* __restrict__ h, const int* __restrict__ t,
            const int* __restrict__ e,
            const float* __restrict__ eb0, const float* __restrict__ eb1,
            const float* __restrict__ eb2, const float* __restrict__ eb3,
            const int* __restrict__ mptr, float* __restrict__ out) {
    __shared__ __align__(16) unsigned long long bkt[NBKT];   // 32KB; cox block only
    __shared__ float smf[2048];
    __shared__ float snm[8], sww[8];
    __shared__ int s_last;
    float* S = (float*)bkt;

    int tid = threadIdx.x;
    int w = tid >> 5, lane = tid & 31;

    if (blockIdx.x == 0) {
        // ================= cox: histogram + warp-suffix-scan + lookup =================
#pragma unroll
        for (int k = 0; k < 16; k++) bkt[tid + k * 256] = 0ull;
        __syncthreads();

        int   tv[16];
        float hv[16];
#pragma unroll
        for (int k = 0; k < 16; k++) {
            int i = tid + k * 256;
            tv[k] = t[i] & (NBKT - 1);
            hv[k] = h[i];
            unsigned long long q = (unsigned long long)(expf(hv[k]) * FXSCALE);
            atomicAdd(&bkt[tv[k]], q);
        }
        __syncthreads();

        float b[16];
        float cs = 0.0f;
#pragma unroll
        for (int j = 0; j < 16; j++) {
            b[j] = (float)bkt[tid * 16 + j] * (1.0f / FXSCALE);
            cs += b[j];
        }
        float suf = cs;
#pragma unroll
        for (int o = 1; o < 32; o <<= 1) {
            float v = __shfl_down_sync(0xffffffffu, suf, o);
            if (lane + o < 32) suf += v;
        }
        if (lane == 0) snm[w] = suf;
        __syncthreads();

        float wse = 0.0f;
        for (int ww = w + 1; ww < 8; ww++) wse += snm[ww];
        float excl = wse + (suf - cs);
        float s = excl;
#pragma unroll
        for (int j = 15; j >= 0; j--) {
            s += b[j];
            S[tid * 16 + j] = s;
        }
        __syncthreads();

        float cp = 0.0f, ef = 0.0f;
#pragma unroll
        for (int k = 0; k < 16; k++) {
            int i = tid + k * 256;
            int ei = e[i];
            ef += (float)ei;
            if (ei) cp += hv[k] - logf(S[tv[k]]);
        }
#pragma unroll
        for (int o = 16; o > 0; o >>= 1) {
            cp += __shfl_xor_sync(0xffffffffu, cp, o);
            ef += __shfl_xor_sync(0xffffffffu, ef, o);
        }
        if (lane == 0) { snm[w] = cp; sww[w] = ef; }
        __syncthreads();
        if (tid == 0) {
            float tc = 0.0f, te = 0.0f;
#pragma unroll
            for (int i = 0; i < 8; i++) { tc += snm[i]; te += sww[i]; }
            g_coxsum = tc; g_efsum = te;
        }
    } else {
        // ================= prep =================
        int pb  = blockIdx.x - 1;
        int mod = pb >> 7;
        int rb  = pb & 127;
        int r0  = rb * RBLK;
        const float* base = (mod == 0) ? eb0 : (mod == 1) ? eb1
                          : (mod == 2) ? eb2 : eb3;

        float4 va[4], vb[4];
#pragma unroll
        for (int rr = 0; rr < 4; rr++) {
            const float4* src = (const float4*)(base + (size_t)(r0 + w * 4 + rr) * DIM);
            va[rr] = src[lane];
            vb[rr] = src[lane + 32];
        }

        float4 acc0 = make_float4(0.f, 0.f, 0.f, 0.f);
        float4 acc1 = make_float4(0.f, 0.f, 0.f, 0.f);
        float nmW = 0.0f, wW = 0.0f;
#pragma unroll
        for (int rr = 0; rr < 4; rr++) {
            float4 v0 = va[rr], v1 = vb[rr];
            float x0 = __shfl_sync(0xffffffffu, v0.x, 0);
            bool eq = (v0.x == x0) && (v0.y == x0) && (v0.z == x0) && (v0.w == x0) &&
                      (v1.x == x0) && (v1.y == x0) && (v1.z == x0) && (v1.w == x0);
            bool miss = (__ballot_sync(0xffffffffu, eq) == 0xffffffffu);

            float ss = v0.x*v0.x + v0.y*v0.y + v0.z*v0.z + v0.w*v0.w
                     + v1.x*v1.x + v1.y*v1.y + v1.z*v1.z + v1.w*v1.w;
#pragma unroll
            for (int o = 16; o > 0; o >>= 1) ss += __shfl_xor_sync(0xffffffffu, ss, o);

            float den = fmaxf(sqrtf(ss), EPSV);
            float inv = miss ? 0.0f : (1.0f / den);
            if (!miss) { nmW += 1.0f; wW += ss / (den * den); }

            acc0.x += v0.x * inv; acc0.y += v0.y * inv;
            acc0.z += v0.z * inv; acc0.w += v0.w * inv;
            acc1.x += v1.x * inv; acc1.y += v1.y * inv;
            acc1.z += v1.z * inv; acc1.w += v1.w * inv;
        }

        float* row = smf + w * 256;
        *(float4*)(row + lane * 4)       = acc0;
        *(float4*)(row + 128 + lane * 4) = acc1;
        if (lane == 0) { snm[w] = nmW; sww[w] = wW; }
        __syncthreads();

        float u = 0.0f;
#pragma unroll
        for (int ww = 0; ww < 8; ww++) u += smf[ww * 256 + tid];
        // deterministic fixed-point accumulation (integer adds commute)
        long long q = (long long)llrintf(u * FXU);
        atomicAdd(&g_uFx[(mod << 8) + tid], (unsigned long long)q);

        if (tid == 0) {
            float V = 0.0f, W = 0.0f;
#pragma unroll
            for (int i = 0; i < 8; i++) { V += snm[i]; W += sww[i]; }
            g_vw[pb] = make_float2(V, W);
        }
    }

    // =================== last-arriving block: combine ===================
    __threadfence();
    if (tid == 0) {
        int c = atomicAdd(&g_count, 1);
        s_last = (c == NBLK - 1);
    }
    __syncthreads();
    if (!s_last) return;

    // total U^2 (additive over mods and cols)
    float us = 0.0f;
#pragma unroll
    for (int m = 0; m < 4; m++) {
        int idx = (m << 8) + tid;
        float u = (float)((long long)g_uFx[idx]) * (1.0f / FXU);
        us += u * u;
        g_uFx[idx] = 0ull;          // reset for next graph replay
    }
#pragma unroll
    for (int o = 16; o > 0; o >>= 1) us += __shfl_xor_sync(0xffffffffu, us, o);
    if (lane == 0) smf[1024 + w] = us;    // avoid snm (maybe in use pre-return? block-local, safe)
    __syncthreads();

    // per-mod V, W from g_vw (512 entries; thread t -> entries t and t+256)
    float2 va2 = g_vw[tid];
    float2 vb2 = g_vw[tid + 256];
    float Va = va2.x, Wa = va2.y, Vb = vb2.x, Wb = vb2.y;
#pragma unroll
    for (int o = 16; o > 0; o >>= 1) {
        Va += __shfl_xor_sync(0xffffffffu, Va, o);
        Wa += __shfl_xor_sync(0xffffffffu, Wa, o);
        Vb += __shfl_xor_sync(0xffffffffu, Vb, o);
        Wb += __shfl_xor_sync(0xffffffffu, Wb, o);
    }
    if (lane == 0) {
        smf[w]      = Va;   // warps 0-3: mod0, warps 4-7: mod1
        smf[8 + w]  = Wa;
        smf[16 + w] = Vb;   // warps 0-3: mod2, warps 4-7: mod3
        smf[24 + w] = Wb;
    }
    __syncthreads();

    if (tid == 0) {
        float U2tot = 0.0f;
#pragma unroll
        for (int i = 0; i < 8; i++) U2tot += smf[1024 + i];

        double sim = 0.0;
#pragma unroll
        for (int m = 0; m < 4; m++) {
            int base = (m & 1) ? 4 : 0;
            int off  = (m >> 1) ? 16 : 0;
            float V = 0.0f, W = 0.0f;
#pragma unroll
            for (int k = 0; k < 4; k++) {
                V += smf[off + base + k];
                W += smf[8 + off + base + k];
            }
            sim += (double)W * (double)V;
        }
        int iv = mptr[0];
        float margin = (iv > -1000000 && iv < 1000000) ? (float)iv : __int_as_float(iv);
        sim += (double)margin * (double)N_PAT * (double)(N_PAT - 1) - (double)U2tot;

        double cox = -(double)g_coxsum / (double)g_efsum;
        out[0] = (float)(sim + cox);
        g_count = 0;                // reset for next graph replay
    }
}

// ---------------- launch ----------------
extern "C" void kernel_launch(void* const* d_in, const int* in_sizes, int n_in,
                              void* d_out, int out_size) {
    const float* h   = (const float*)d_in[0];
    const int*   t   = (const int*)d_in[1];
    const int*   e   = (const int*)d_in[2];
    const float* eb0 = (const float*)d_in[3];
    const float* eb1 = (const float*)d_in[4];
    const float* eb2 = (const float*)d_in[5];
    const float* eb3 = (const float*)d_in[6];
    const int*   mg  = (const int*)d_in[7];
    float* out = (float*)d_out;

    main_kernel<<<NBLK, 256>>>(h, t, e, eb0, eb1, eb2, eb3, mg, out);
}

// round 15
// speedup vs baseline: 1.4864x; 1.3102x over previous
#include <cuda_runtime.h>
#include <math.h>
#include <stdint.h>

#define N_PAT 4096
#define DIM   256
#define EPSV  1e-8f
#define RBLK  32                  // rows per prep block
#define NRB   (N_PAT / RBLK)      // 128 row-blocks per modality
#define NPREP (4 * NRB)           // 512 prep blocks
#define NBLK  (NPREP + 1)         // + cox block
#define NBKT  4096
#define FXSCALE 262144.0f         // 2^18 fixed-point for cox histogram (u32)
#define FXU     16777216.0f       // 2^24 fixed-point for u accumulators

// ---------------- static scratch ----------------
__device__ unsigned long long g_uFx[4 * DIM];   // per (mod,col) fixed-point u sum
__device__ float2 g_vw[NPREP];                  // per (mod,rowblock) (V,W)
__device__ float  g_coxsum, g_efsum;
__device__ int    g_count;                      // arrival counter (reset by last block)

// ---------------- cold combine tail (registers isolated via noinline) ----------------
__device__ __noinline__ void combine_tail(const int* __restrict__ mptr,
                                          float* __restrict__ out) {
    __shared__ float sU[8];
    __shared__ float sVW[32];
    int tid = threadIdx.x;
    int w = tid >> 5, lane = tid & 31;

    // total U^2 (additive over mods and cols)
    float us = 0.0f;
#pragma unroll
    for (int m = 0; m < 4; m++) {
        int idx = (m << 8) + tid;
        float u = (float)((long long)g_uFx[idx]) * (1.0f / FXU);
        us += u * u;
        g_uFx[idx] = 0ull;          // reset for next graph replay
    }
#pragma unroll
    for (int o = 16; o > 0; o >>= 1) us += __shfl_xor_sync(0xffffffffu, us, o);
    if (lane == 0) sU[w] = us;

    // per-mod V, W from g_vw (512 entries; thread t -> entries t and t+256)
    float2 va2 = g_vw[tid];
    float2 vb2 = g_vw[tid + 256];
    float Va = va2.x, Wa = va2.y, Vb = vb2.x, Wb = vb2.y;
#pragma unroll
    for (int o = 16; o > 0; o >>= 1) {
        Va += __shfl_xor_sync(0xffffffffu, Va, o);
        Wa += __shfl_xor_sync(0xffffffffu, Wa, o);
        Vb += __shfl_xor_sync(0xffffffffu, Vb, o);
        Wb += __shfl_xor_sync(0xffffffffu, Wb, o);
    }
    if (lane == 0) {
        sVW[w]      = Va;   // warps 0-3: mod0 ; warps 4-7: mod1
        sVW[8 + w]  = Wa;
        sVW[16 + w] = Vb;   // warps 0-3: mod2 ; warps 4-7: mod3
        sVW[24 + w] = Wb;
    }
    __syncthreads();

    if (tid == 0) {
        float U2tot = 0.0f;
#pragma unroll
        for (int i = 0; i < 8; i++) U2tot += sU[i];

        double sim = 0.0;
#pragma unroll
        for (int m = 0; m < 4; m++) {
            int base = (m & 1) ? 4 : 0;
            int off  = (m >> 1) ? 16 : 0;
            float V = 0.0f, W = 0.0f;
#pragma unroll
            for (int k = 0; k < 4; k++) {
                V += sVW[off + base + k];
                W += sVW[8 + off + base + k];
            }
            sim += (double)W * (double)V;
        }
        int iv = mptr[0];
        float margin = (iv > -1000000 && iv < 1000000) ? (float)iv : __int_as_float(iv);
        sim += (double)margin * (double)N_PAT * (double)(N_PAT - 1) - (double)U2tot;

        double cox = -(double)g_coxsum / (double)g_efsum;
        out[0] = (float)(sim + cox);
        g_count = 0;                // reset for next graph replay
    }
}

// =================== single kernel: cox + prep + last-block combine ===================
__global__ void __launch_bounds__(256, 5)
main_kernel(const float* __restrict__ h, const int* __restrict__ t,
            const int* __restrict__ e,
            const float* __restrict__ eb0, const float* __restrict__ eb1,
            const float* __restrict__ eb2, const float* __restrict__ eb3,
            const int* __restrict__ mptr, float* __restrict__ out) {
    __shared__ __align__(16) unsigned int bkt[NBKT];   // 16KB; cox block only
    __shared__ float smf[2048];
    __shared__ float snm[8], sww[8];
    __shared__ int s_last;
    float* S = (float*)bkt;

    int tid = threadIdx.x;
    int w = tid >> 5, lane = tid & 31;

    if (blockIdx.x == 0) {
        // ================= cox: histogram + warp-suffix-scan + lookup =================
#pragma unroll
        for (int k = 0; k < 16; k++) bkt[tid + k * 256] = 0u;
        __syncthreads();

        int   tv[16];
        float hv[16];
#pragma unroll
        for (int k = 0; k < 16; k++) {
            int i = tid + k * 256;
            tv[k] = t[i] & (NBKT - 1);
            hv[k] = h[i];
            unsigned int q = (unsigned int)(expf(hv[k]) * FXSCALE);
            atomicAdd(&bkt[tv[k]], q);
        }
        __syncthreads();

        float b[16];
        float cs = 0.0f;
#pragma unroll
        for (int j = 0; j < 16; j++) {
            b[j] = (float)bkt[tid * 16 + j] * (1.0f / FXSCALE);
            cs += b[j];
        }
        float suf = cs;
#pragma unroll
        for (int o = 1; o < 32; o <<= 1) {
            float v = __shfl_down_sync(0xffffffffu, suf, o);
            if (lane + o < 32) suf += v;
        }
        if (lane == 0) snm[w] = suf;
        __syncthreads();

        float wse = 0.0f;
        for (int ww = w + 1; ww < 8; ww++) wse += snm[ww];
        float excl = wse + (suf - cs);
        float s = excl;
#pragma unroll
        for (int j = 15; j >= 0; j--) {
            s += b[j];
            S[tid * 16 + j] = s;
        }
        __syncthreads();

        float cp = 0.0f, ef = 0.0f;
#pragma unroll
        for (int k = 0; k < 16; k++) {
            int i = tid + k * 256;
            int ei = e[i];
            ef += (float)ei;
            if (ei) cp += hv[k] - logf(S[tv[k]]);
        }
#pragma unroll
        for (int o = 16; o > 0; o >>= 1) {
            cp += __shfl_xor_sync(0xffffffffu, cp, o);
            ef += __shfl_xor_sync(0xffffffffu, ef, o);
        }
        if (lane == 0) { snm[w] = cp; sww[w] = ef; }
        __syncthreads();
        if (tid == 0) {
            float tc = 0.0f, te = 0.0f;
#pragma unroll
            for (int i = 0; i < 8; i++) { tc += snm[i]; te += sww[i]; }
            g_coxsum = tc; g_efsum = te;
        }
    } else {
        // ================= prep =================
        int pb  = blockIdx.x - 1;
        int mod = pb >> 7;
        int rb  = pb & 127;
        int r0  = rb * RBLK;
        const float* base = (mod == 0) ? eb0 : (mod == 1) ? eb1
                          : (mod == 2) ? eb2 : eb3;

        float4 va[4], vb[4];
#pragma unroll
        for (int rr = 0; rr < 4; rr++) {
            const float4* src = (const float4*)(base + (size_t)(r0 + w * 4 + rr) * DIM);
            va[rr] = src[lane];
            vb[rr] = src[lane + 32];
        }

        float4 acc0 = make_float4(0.f, 0.f, 0.f, 0.f);
        float4 acc1 = make_float4(0.f, 0.f, 0.f, 0.f);
        float nmW = 0.0f, wW = 0.0f;
#pragma unroll
        for (int rr = 0; rr < 4; rr++) {
            float4 v0 = va[rr], v1 = vb[rr];
            float x0 = __shfl_sync(0xffffffffu, v0.x, 0);
            bool eq = (v0.x == x0) && (v0.y == x0) && (v0.z == x0) && (v0.w == x0) &&
                      (v1.x == x0) && (v1.y == x0) && (v1.z == x0) && (v1.w == x0);
            bool miss = (__ballot_sync(0xffffffffu, eq) == 0xffffffffu);

            float ss = v0.x*v0.x + v0.y*v0.y + v0.z*v0.z + v0.w*v0.w
                     + v1.x*v1.x + v1.y*v1.y + v1.z*v1.z + v1.w*v1.w;
#pragma unroll
            for (int o = 16; o > 0; o >>= 1) ss += __shfl_xor_sync(0xffffffffu, ss, o);

            float den = fmaxf(sqrtf(ss), EPSV);
            float inv = miss ? 0.0f : (1.0f / den);
            if (!miss) { nmW += 1.0f; wW += ss / (den * den); }

            acc0.x += v0.x * inv; acc0.y += v0.y * inv;
            acc0.z += v0.z * inv; acc0.w += v0.w * inv;
            acc1.x += v1.x * inv; acc1.y += v1.y * inv;
            acc1.z += v1.z * inv; acc1.w += v1.w * inv;
        }

        float* row = smf + w * 256;
        *(float4*)(row + lane * 4)       = acc0;
        *(float4*)(row + 128 + lane * 4) = acc1;
        if (lane == 0) { snm[w] = nmW; sww[w] = wW; }
        __syncthreads();

        float u = 0.0f;
#pragma unroll
        for (int ww = 0; ww < 8; ww++) u += smf[ww * 256 + tid];
        // deterministic fixed-point accumulation (integer adds commute)
        long long q = (long long)llrintf(u * FXU);
        atomicAdd(&g_uFx[(mod << 8) + tid], (unsigned long long)q);

        if (tid == 0) {
            float V = 0.0f, W = 0.0f;
#pragma unroll
            for (int i = 0; i < 8; i++) { V += snm[i]; W += sww[i]; }
            g_vw[pb] = make_float2(V, W);
        }
    }

    // =================== last-arriving block: combine ===================
    __threadfence();
    if (tid == 0) {
        int c = atomicAdd(&g_count, 1);
        s_last = (c == NBLK - 1);
    }
    __syncthreads();
    if (!s_last) return;

    combine_tail(mptr, out);
}

// ---------------- launch ----------------
extern "C" void kernel_launch(void* const* d_in, const int* in_sizes, int n_in,
                              void* d_out, int out_size) {
    const float* h   = (const float*)d_in[0];
    const int*   t   = (const int*)d_in[1];
    const int*   e   = (const int*)d_in[2];
    const float* eb0 = (const float*)d_in[3];
    const float* eb1 = (const float*)d_in[4];
    const float* eb2 = (const float*)d_in[5];
    const float* eb3 = (const float*)d_in[6];
    const int*   mg  = (const int*)d_in[7];
    float* out = (float*)d_out;

    main_kernel<<<NBLK, 256>>>(h, t, e, eb0, eb1, eb2, eb3, mg, out);
}